// round 1
// baseline (speedup 1.0000x reference)
#include <cuda_runtime.h>
#include <math.h>

#define NLEV   16
#define TSZ    524288           // 2^19 hash table entries per level
#define NFEAT  2
#define HIDDEN 64
#define FEAT   13
#define DIN    35               // 3 + 16*2

// ---------------------------------------------------------------------------
// Normalized (weight-norm applied) weights, stored TRANSPOSED for float4
// inner loops over outputs. Filled by prep_kernel each launch.
// ---------------------------------------------------------------------------
__device__ float g_W0T[DIN][HIDDEN];      // [in][out]
__device__ float g_W1T[HIDDEN][HIDDEN];   // [in][out]
__device__ float g_W2T[HIDDEN][16];       // [in][out], out padded 13->16
__device__ float g_b0[HIDDEN];
__device__ float g_b1[HIDDEN];
__device__ float g_b2[16];

__global__ void prep_kernel(const float* __restrict__ V0, const float* __restrict__ g0, const float* __restrict__ b0,
                            const float* __restrict__ V1, const float* __restrict__ g1, const float* __restrict__ b1,
                            const float* __restrict__ V2, const float* __restrict__ g2, const float* __restrict__ b2)
{
    int o = threadIdx.x;
    if (o < HIDDEN) {
        float s = 0.f;
        for (int i = 0; i < DIN; i++) { float v = V0[o * DIN + i]; s += v * v; }
        float sc = g0[o] / sqrtf(s);
        for (int i = 0; i < DIN; i++) g_W0T[i][o] = V0[o * DIN + i] * sc;
        g_b0[o] = b0[o];

        s = 0.f;
        for (int i = 0; i < HIDDEN; i++) { float v = V1[o * HIDDEN + i]; s += v * v; }
        sc = g1[o] / sqrtf(s);
        for (int i = 0; i < HIDDEN; i++) g_W1T[i][o] = V1[o * HIDDEN + i] * sc;
        g_b1[o] = b1[o];
    }
    if (o < 16) {
        if (o < FEAT) {
            float s = 0.f;
            for (int i = 0; i < HIDDEN; i++) { float v = V2[o * HIDDEN + i]; s += v * v; }
            float sc = g2[o] / sqrtf(s);
            for (int i = 0; i < HIDDEN; i++) g_W2T[i][o] = V2[o * HIDDEN + i] * sc;
            g_b2[o] = b2[o];
        } else {
            for (int i = 0; i < HIDDEN; i++) g_W2T[i][o] = 0.f;
            g_b2[o] = 0.f;
        }
    }
}

struct GridParams { int gs[NLEV]; };

__device__ __forceinline__ float softplus100(float z)
{
    // jax.nn.softplus(100*z)/100 == (max(x,0) + log1p(exp(-|x|)))/100, x = 100 z
    float x = 100.f * z;
    return (fmaxf(x, 0.f) + log1pf(__expf(-fabsf(x)))) * 0.01f;
}

__global__ __launch_bounds__(128)
void sdf_kernel(const float* __restrict__ points,
                const float* __restrict__ table,
                float* __restrict__ out,
                int n, GridParams gp)
{
    __shared__ float sW0[DIN][HIDDEN];
    __shared__ float sW1[HIDDEN][HIDDEN];
    __shared__ float sW2[HIDDEN][16];
    __shared__ float sb0[HIDDEN];
    __shared__ float sb1[HIDDEN];
    __shared__ float sb2[16];

    const int tid = threadIdx.x;
    for (int i = tid; i < DIN * HIDDEN;    i += 128) (&sW0[0][0])[i] = (&g_W0T[0][0])[i];
    for (int i = tid; i < HIDDEN * HIDDEN; i += 128) (&sW1[0][0])[i] = (&g_W1T[0][0])[i];
    for (int i = tid; i < HIDDEN * 16;     i += 128) (&sW2[0][0])[i] = (&g_W2T[0][0])[i];
    if (tid < HIDDEN) { sb0[tid] = g_b0[tid]; sb1[tid] = g_b1[tid]; }
    if (tid < 16)     { sb2[tid] = g_b2[tid]; }
    __syncthreads();

    const int p = blockIdx.x * 128 + tid;
    if (p >= n) return;

    const float px = points[3 * p + 0];
    const float py = points[3 * p + 1];
    const float pz = points[3 * p + 2];
    const float ux = fminf(fmaxf((px + 1.f) * 0.5f, 0.f), 1.f);
    const float uy = fminf(fmaxf((py + 1.f) * 0.5f, 0.f), 1.f);
    const float uz = fminf(fmaxf((pz + 1.f) * 0.5f, 0.f), 1.f);

    // ---- layer 0 accumulator, fed incrementally -------------------------
    float acc[HIDDEN];
    #pragma unroll
    for (int o = 0; o < HIDDEN; o++) acc[o] = sb0[o];
    #pragma unroll
    for (int o = 0; o < HIDDEN; o += 4) {
        float4 wa = *(const float4*)&sW0[0][o];
        float4 wb = *(const float4*)&sW0[1][o];
        float4 wc = *(const float4*)&sW0[2][o];
        acc[o + 0] += px * wa.x + py * wb.x + pz * wc.x;
        acc[o + 1] += px * wa.y + py * wb.y + pz * wc.y;
        acc[o + 2] += px * wa.z + py * wb.z + pz * wc.z;
        acc[o + 3] += px * wa.w + py * wb.w + pz * wc.w;
    }

    const float2* __restrict__ tab = (const float2*)table;

    #pragma unroll 1
    for (int lv = 0; lv < NLEV; lv++) {
        const int gs = gp.gs[lv];
        const float gm1 = (float)(gs - 1);
        const float fx = ux * gm1, fy = uy * gm1, fz = uz * gm1;
        int ix = (int)floorf(fx); ix = min(max(ix, 0), gs - 2);
        int iy = (int)floorf(fy); iy = min(max(iy, 0), gs - 2);
        int iz = (int)floorf(fz); iz = min(max(iz, 0), gs - 2);
        const float wx = fx - (float)ix;
        const float wy = fy - (float)iy;
        const float wz = fz - (float)iz;
        const bool dense = ((long long)gs * gs * gs <= (long long)TSZ);
        const float2* __restrict__ tb = tab + (size_t)lv * TSZ;

        float f0 = 0.f, f1 = 0.f;
        #pragma unroll
        for (int c = 0; c < 8; c++) {
            const int i = (c >> 2) & 1, j = (c >> 1) & 1, k = c & 1;
            const int cx = ix + i, cy = iy + j, cz = iz + k;
            unsigned idx;
            if (dense) {
                idx = (unsigned)(cx + gs * (cy + gs * cz));
            } else {
                idx = ((unsigned)cx * 1u ^ (unsigned)cy * 2654435761u ^ (unsigned)cz * 805459861u)
                      & (unsigned)(TSZ - 1);
            }
            const float2 f = __ldg(&tb[idx]);
            const float tx = i ? wx : 1.f - wx;
            const float ty = j ? wy : 1.f - wy;
            const float tz = k ? wz : 1.f - wz;
            const float w = (tx * ty) * tz;
            f0 += f.x * w;
            f1 += f.y * w;
        }

        const int r = 3 + 2 * lv;
        #pragma unroll
        for (int o = 0; o < HIDDEN; o += 4) {
            float4 wa = *(const float4*)&sW0[r][o];
            float4 wb = *(const float4*)&sW0[r + 1][o];
            acc[o + 0] += f0 * wa.x + f1 * wb.x;
            acc[o + 1] += f0 * wa.y + f1 * wb.y;
            acc[o + 2] += f0 * wa.z + f1 * wb.z;
            acc[o + 3] += f0 * wa.w + f1 * wb.w;
        }
    }

    #pragma unroll
    for (int o = 0; o < HIDDEN; o++) acc[o] = softplus100(acc[o]);

    // ---- layer 1 --------------------------------------------------------
    float acc1[HIDDEN];
    #pragma unroll
    for (int o = 0; o < HIDDEN; o++) acc1[o] = sb1[o];
    #pragma unroll 4
    for (int i = 0; i < HIDDEN; i++) {
        const float hi = acc[i];
        #pragma unroll
        for (int o = 0; o < HIDDEN; o += 4) {
            float4 w = *(const float4*)&sW1[i][o];
            acc1[o + 0] += hi * w.x;
            acc1[o + 1] += hi * w.y;
            acc1[o + 2] += hi * w.z;
            acc1[o + 3] += hi * w.w;
        }
    }
    #pragma unroll
    for (int o = 0; o < HIDDEN; o++) acc1[o] = softplus100(acc1[o]);

    // ---- layer 2 --------------------------------------------------------
    float acc2[16];
    #pragma unroll
    for (int o = 0; o < 16; o++) acc2[o] = sb2[o];
    #pragma unroll 8
    for (int i = 0; i < HIDDEN; i++) {
        const float hi = acc1[i];
        #pragma unroll
        for (int o = 0; o < 16; o += 4) {
            float4 w = *(const float4*)&sW2[i][o];
            acc2[o + 0] += hi * w.x;
            acc2[o + 1] += hi * w.y;
            acc2[o + 2] += hi * w.z;
            acc2[o + 3] += hi * w.w;
        }
    }

    // ---- outputs: sdf (n floats), then h (n x 13) -----------------------
    out[p] = acc2[0];
    float* __restrict__ hout = out + n + (size_t)p * FEAT;
    #pragma unroll
    for (int j = 0; j < FEAT; j++) hout[j] = acc2[j];
}

extern "C" void kernel_launch(void* const* d_in, const int* in_sizes, int n_in,
                              void* d_out, int out_size)
{
    const float* points = (const float*)d_in[0];
    const float* table  = (const float*)d_in[1];
    const float* V0 = (const float*)d_in[2];
    const float* g0 = (const float*)d_in[3];
    const float* b0 = (const float*)d_in[4];
    const float* V1 = (const float*)d_in[5];
    const float* g1 = (const float*)d_in[6];
    const float* b1 = (const float*)d_in[7];
    const float* V2 = (const float*)d_in[8];
    const float* g2 = (const float*)d_in[9];
    const float* b2 = (const float*)d_in[10];
    float* out = (float*)d_out;

    const int n = in_sizes[0] / 3;

    // Grid sizes: identical double-precision sequence to the numpy reference.
    GridParams gp;
    const double scale = exp((log(2048.0) - log(16.0)) / 15.0);
    for (int lv = 0; lv < NLEV; lv++)
        gp.gs[lv] = (int)floor(16.0 * pow(scale, (double)lv)) + 1;

    prep_kernel<<<1, 64>>>(V0, g0, b0, V1, g1, b1, V2, g2, b2);

    const int blocks = (n + 127) / 128;
    sdf_kernel<<<blocks, 128>>>(points, table, out, n, gp);
}

// round 2
// speedup vs baseline: 1.2302x; 1.2302x over previous
#include <cuda_runtime.h>
#include <math.h>

#define NLEV   16
#define TSZ    524288
#define HIDDEN 64
#define FEAT   13
#define DIN    35

typedef unsigned long long u64;

// ---------------------------------------------------------------------------
// Packed f32x2 helpers (sm_103a FFMA2 — only reachable via PTX)
// ---------------------------------------------------------------------------
__device__ __forceinline__ u64 pack2(float lo, float hi) {
    u64 r; asm("mov.b64 %0, {%1, %2};" : "=l"(r) : "f"(lo), "f"(hi)); return r;
}
__device__ __forceinline__ u64 bcast2(float v) { return pack2(v, v); }
__device__ __forceinline__ u64 fma2(u64 a, u64 b, u64 c) {
    u64 d; asm("fma.rn.f32x2 %0, %1, %2, %3;" : "=l"(d) : "l"(a), "l"(b), "l"(c)); return d;
}
__device__ __forceinline__ void unpack2(u64 v, float& lo, float& hi) {
    asm("mov.b64 {%0, %1}, %2;" : "=f"(lo), "=f"(hi) : "l"(v));
}

// ---------------------------------------------------------------------------
// Normalized weights, transposed [in][out], filled by prep_kernel.
// ---------------------------------------------------------------------------
__device__ float g_W0T[DIN][HIDDEN];
__device__ float g_W1T[HIDDEN][HIDDEN];
__device__ float g_W2T[HIDDEN][16];
__device__ float g_b0[HIDDEN];
__device__ float g_b1[HIDDEN];
__device__ float g_b2[16];

__global__ void prep_kernel(const float* __restrict__ V0, const float* __restrict__ g0, const float* __restrict__ b0,
                            const float* __restrict__ V1, const float* __restrict__ g1, const float* __restrict__ b1,
                            const float* __restrict__ V2, const float* __restrict__ g2, const float* __restrict__ b2)
{
    int o = threadIdx.x;
    if (o < HIDDEN) {
        float s = 0.f;
        for (int i = 0; i < DIN; i++) { float v = V0[o * DIN + i]; s += v * v; }
        float sc = g0[o] / sqrtf(s);
        for (int i = 0; i < DIN; i++) g_W0T[i][o] = V0[o * DIN + i] * sc;
        g_b0[o] = b0[o];

        s = 0.f;
        for (int i = 0; i < HIDDEN; i++) { float v = V1[o * HIDDEN + i]; s += v * v; }
        sc = g1[o] / sqrtf(s);
        for (int i = 0; i < HIDDEN; i++) g_W1T[i][o] = V1[o * HIDDEN + i] * sc;
        g_b1[o] = b1[o];
    }
    if (o < 16) {
        if (o < FEAT) {
            float s = 0.f;
            for (int i = 0; i < HIDDEN; i++) { float v = V2[o * HIDDEN + i]; s += v * v; }
            float sc = g2[o] / sqrtf(s);
            for (int i = 0; i < HIDDEN; i++) g_W2T[i][o] = V2[o * HIDDEN + i] * sc;
            g_b2[o] = b2[o];
        } else {
            for (int i = 0; i < HIDDEN; i++) g_W2T[i][o] = 0.f;
            g_b2[o] = 0.f;
        }
    }
}

struct GridParams { int gs[NLEV]; };

__device__ __forceinline__ float softplus100(float z)
{
    float x = 100.f * z;
    return (fmaxf(x, 0.f) + log1pf(__expf(-fabsf(x)))) * 0.01f;
}

__global__ __launch_bounds__(128)
void sdf_kernel(const float* __restrict__ points,
                const float* __restrict__ table,
                float* __restrict__ out,
                int n, GridParams gp)
{
    // Weights in shared, pair-addressable as u64 (8B aligned rows of 64/16 floats)
    __shared__ float sW0[DIN][HIDDEN];
    __shared__ float sW1[HIDDEN][HIDDEN];
    __shared__ float sW2[HIDDEN][16];
    __shared__ float sb0[HIDDEN];
    __shared__ float sb1[HIDDEN];
    __shared__ float sb2[16];

    const int tid = threadIdx.x;
    for (int i = tid; i < DIN * HIDDEN;    i += 128) (&sW0[0][0])[i] = (&g_W0T[0][0])[i];
    for (int i = tid; i < HIDDEN * HIDDEN; i += 128) (&sW1[0][0])[i] = (&g_W1T[0][0])[i];
    for (int i = tid; i < HIDDEN * 16;     i += 128) (&sW2[0][0])[i] = (&g_W2T[0][0])[i];
    if (tid < HIDDEN) { sb0[tid] = g_b0[tid]; sb1[tid] = g_b1[tid]; }
    if (tid < 16)     { sb2[tid] = g_b2[tid]; }
    __syncthreads();

    const int p = blockIdx.x * 128 + tid;
    if (p >= n) return;

    const float px = points[3 * p + 0];
    const float py = points[3 * p + 1];
    const float pz = points[3 * p + 2];
    const float ux = fminf(fmaxf((px + 1.f) * 0.5f, 0.f), 1.f);
    const float uy = fminf(fmaxf((py + 1.f) * 0.5f, 0.f), 1.f);
    const float uz = fminf(fmaxf((pz + 1.f) * 0.5f, 0.f), 1.f);

    // ---- layer 0: 32 packed accumulators --------------------------------
    u64 acc[32];
    {
        const u64* b = (const u64*)sb0;
        #pragma unroll
        for (int j = 0; j < 32; j++) acc[j] = b[j];
    }
    {
        const u64* wa = (const u64*)&sW0[0][0];
        const u64* wb = (const u64*)&sW0[1][0];
        const u64* wc = (const u64*)&sW0[2][0];
        const u64 bx = bcast2(px), by = bcast2(py), bz = bcast2(pz);
        #pragma unroll
        for (int j = 0; j < 32; j++) {
            acc[j] = fma2(bx, wa[j], acc[j]);
            acc[j] = fma2(by, wb[j], acc[j]);
            acc[j] = fma2(bz, wc[j], acc[j]);
        }
    }

    const float2* __restrict__ tab = (const float2*)table;

    #pragma unroll 1
    for (int lv = 0; lv < NLEV; lv++) {
        const int gs = gp.gs[lv];
        const float gm1 = (float)(gs - 1);
        const float fx = ux * gm1, fy = uy * gm1, fz = uz * gm1;
        int ix = (int)floorf(fx); ix = min(max(ix, 0), gs - 2);
        int iy = (int)floorf(fy); iy = min(max(iy, 0), gs - 2);
        int iz = (int)floorf(fz); iz = min(max(iz, 0), gs - 2);
        const float wx = fx - (float)ix;
        const float wy = fy - (float)iy;
        const float wz = fz - (float)iz;
        const bool dense = ((long long)gs * gs * gs <= (long long)TSZ);
        const float2* __restrict__ tb = tab + (size_t)lv * TSZ;

        // Batch: compute all 8 indices, then issue all 8 loads (max MLP)
        unsigned idxs[8];
        #pragma unroll
        for (int c = 0; c < 8; c++) {
            const int i = (c >> 2) & 1, j = (c >> 1) & 1, k = c & 1;
            const int cx = ix + i, cy = iy + j, cz = iz + k;
            if (dense) {
                idxs[c] = (unsigned)(cx + gs * (cy + gs * cz));
            } else {
                idxs[c] = ((unsigned)cx * 1u ^ (unsigned)cy * 2654435761u ^ (unsigned)cz * 805459861u)
                          & (unsigned)(TSZ - 1);
            }
        }
        float2 f[8];
        #pragma unroll
        for (int c = 0; c < 8; c++) f[c] = __ldg(&tb[idxs[c]]);

        float f0 = 0.f, f1 = 0.f;
        #pragma unroll
        for (int c = 0; c < 8; c++) {
            const int i = (c >> 2) & 1, j = (c >> 1) & 1, k = c & 1;
            const float tx = i ? wx : 1.f - wx;
            const float ty = j ? wy : 1.f - wy;
            const float tz = k ? wz : 1.f - wz;
            const float w = (tx * ty) * tz;
            f0 += f[c].x * w;
            f1 += f[c].y * w;
        }

        const int r = 3 + 2 * lv;
        const u64* wa = (const u64*)&sW0[r][0];
        const u64* wb = (const u64*)&sW0[r + 1][0];
        const u64 b0v = bcast2(f0), b1v = bcast2(f1);
        #pragma unroll
        for (int j = 0; j < 32; j++) {
            acc[j] = fma2(b0v, wa[j], acc[j]);
            acc[j] = fma2(b1v, wb[j], acc[j]);
        }
    }

    // softplus -> scalar h[64]
    float h[HIDDEN];
    #pragma unroll
    for (int j = 0; j < 32; j++) {
        float lo, hi; unpack2(acc[j], lo, hi);
        h[2 * j]     = softplus100(lo);
        h[2 * j + 1] = softplus100(hi);
    }

    // ---- layer 1 --------------------------------------------------------
    u64 acc1[32];
    {
        const u64* b = (const u64*)sb1;
        #pragma unroll
        for (int j = 0; j < 32; j++) acc1[j] = b[j];
    }
    #pragma unroll 4
    for (int i = 0; i < HIDDEN; i++) {
        const u64 hb = bcast2(h[i]);
        const u64* w = (const u64*)&sW1[i][0];
        #pragma unroll
        for (int j = 0; j < 32; j++) acc1[j] = fma2(hb, w[j], acc1[j]);
    }
    float h1[HIDDEN];
    #pragma unroll
    for (int j = 0; j < 32; j++) {
        float lo, hi; unpack2(acc1[j], lo, hi);
        h1[2 * j]     = softplus100(lo);
        h1[2 * j + 1] = softplus100(hi);
    }

    // ---- layer 2 --------------------------------------------------------
    u64 acc2[8];
    {
        const u64* b = (const u64*)sb2;
        #pragma unroll
        for (int j = 0; j < 8; j++) acc2[j] = b[j];
    }
    #pragma unroll 8
    for (int i = 0; i < HIDDEN; i++) {
        const u64 hb = bcast2(h1[i]);
        const u64* w = (const u64*)&sW2[i][0];
        #pragma unroll
        for (int j = 0; j < 8; j++) acc2[j] = fma2(hb, w[j], acc2[j]);
    }

    float o2[16];
    #pragma unroll
    for (int j = 0; j < 8; j++) unpack2(acc2[j], o2[2 * j], o2[2 * j + 1]);

    // ---- outputs: sdf (n floats), then h (n x 13) -----------------------
    out[p] = o2[0];
    float* __restrict__ hout = out + n + (size_t)p * FEAT;
    #pragma unroll
    for (int j = 0; j < FEAT; j++) hout[j] = o2[j];
}

extern "C" void kernel_launch(void* const* d_in, const int* in_sizes, int n_in,
                              void* d_out, int out_size)
{
    const float* points = (const float*)d_in[0];
    const float* table  = (const float*)d_in[1];
    const float* V0 = (const float*)d_in[2];
    const float* g0 = (const float*)d_in[3];
    const float* b0 = (const float*)d_in[4];
    const float* V1 = (const float*)d_in[5];
    const float* g1 = (const float*)d_in[6];
    const float* b1 = (const float*)d_in[7];
    const float* V2 = (const float*)d_in[8];
    const float* g2 = (const float*)d_in[9];
    const float* b2 = (const float*)d_in[10];
    float* out = (float*)d_out;

    const int n = in_sizes[0] / 3;

    GridParams gp;
    const double scale = exp((log(2048.0) - log(16.0)) / 15.0);
    for (int lv = 0; lv < NLEV; lv++)
        gp.gs[lv] = (int)floor(16.0 * pow(scale, (double)lv)) + 1;

    prep_kernel<<<1, 64>>>(V0, g0, b0, V1, g1, b1, V2, g2, b2);

    const int blocks = (n + 127) / 128;
    sdf_kernel<<<blocks, 128>>>(points, table, out, n, gp);
}

// round 5
// speedup vs baseline: 1.4409x; 1.1713x over previous
#include <cuda_runtime.h>
#include <math.h>

#define NLEV   16
#define TSZ    524288
#define HIDDEN 64
#define FEAT   13
#define DIN    35

typedef unsigned long long u64;

__device__ __forceinline__ u64 pack2(float lo, float hi) {
    u64 r; asm("mov.b64 %0, {%1, %2};" : "=l"(r) : "f"(lo), "f"(hi)); return r;
}
__device__ __forceinline__ u64 bcast2(float v) { return pack2(v, v); }
__device__ __forceinline__ u64 fma2(u64 a, u64 b, u64 c) {
    u64 d; asm("fma.rn.f32x2 %0, %1, %2, %3;" : "=l"(d) : "l"(a), "l"(b), "l"(c)); return d;
}
__device__ __forceinline__ void unpack2(u64 v, float& lo, float& hi) {
    asm("mov.b64 {%0, %1}, %2;" : "=f"(lo), "=f"(hi) : "l"(v));
}

// ---------------------------------------------------------------------------
__device__ float g_W0T[DIN][HIDDEN];
__device__ float g_W1T[HIDDEN][HIDDEN];
__device__ float g_W2T[HIDDEN][16];
__device__ float g_b0[HIDDEN];
__device__ float g_b1[HIDDEN];
__device__ float g_b2[16];

__global__ void prep_kernel(const float* __restrict__ V0, const float* __restrict__ g0, const float* __restrict__ b0,
                            const float* __restrict__ V1, const float* __restrict__ g1, const float* __restrict__ b1,
                            const float* __restrict__ V2, const float* __restrict__ g2, const float* __restrict__ b2)
{
    int o = threadIdx.x;
    if (o < HIDDEN) {
        float s = 0.f;
        for (int i = 0; i < DIN; i++) { float v = V0[o * DIN + i]; s += v * v; }
        float sc = g0[o] / sqrtf(s);
        for (int i = 0; i < DIN; i++) g_W0T[i][o] = V0[o * DIN + i] * sc;
        g_b0[o] = b0[o];

        s = 0.f;
        for (int i = 0; i < HIDDEN; i++) { float v = V1[o * HIDDEN + i]; s += v * v; }
        sc = g1[o] / sqrtf(s);
        for (int i = 0; i < HIDDEN; i++) g_W1T[i][o] = V1[o * HIDDEN + i] * sc;
        g_b1[o] = b1[o];
    }
    if (o < 16) {
        if (o < FEAT) {
            float s = 0.f;
            for (int i = 0; i < HIDDEN; i++) { float v = V2[o * HIDDEN + i]; s += v * v; }
            float sc = g2[o] / sqrtf(s);
            for (int i = 0; i < HIDDEN; i++) g_W2T[i][o] = V2[o * HIDDEN + i] * sc;
            g_b2[o] = b2[o];
        } else {
            for (int i = 0; i < HIDDEN; i++) g_W2T[i][o] = 0.f;
            g_b2[o] = 0.f;
        }
    }
}

struct GridParams { int gs[NLEV]; };

__device__ __forceinline__ float softplus100(float z)
{
    float x = 100.f * z;
    return (fmaxf(x, 0.f) + log1pf(__expf(-fabsf(x)))) * 0.01f;
}

// Corner order: c = i*4 + j*2 + k (matches reference OFFSETS loop nest).
__device__ __forceinline__ void level_setup(int gs, float ux, float uy, float uz,
                                            unsigned idxs[8], float& wx, float& wy, float& wz)
{
    const float gm1 = (float)(gs - 1);
    const float fx = ux * gm1, fy = uy * gm1, fz = uz * gm1;
    int ix = (int)floorf(fx); ix = min(max(ix, 0), gs - 2);
    int iy = (int)floorf(fy); iy = min(max(iy, 0), gs - 2);
    int iz = (int)floorf(fz); iz = min(max(iz, 0), gs - 2);
    wx = fx - (float)ix;
    wy = fy - (float)iy;
    wz = fz - (float)iz;

    if ((long long)gs * gs * gs <= (long long)TSZ) {
        const int g1 = gs, g2 = gs * gs;
        const int base = ix + g1 * iy + g2 * iz;
        idxs[0] = base;
        idxs[1] = base + g2;
        idxs[2] = base + g1;
        idxs[3] = base + g1 + g2;
        idxs[4] = base + 1;
        idxs[5] = base + 1 + g2;
        idxs[6] = base + 1 + g1;
        idxs[7] = base + 1 + g1 + g2;
    } else {
        const unsigned hx0 = (unsigned)ix,               hx1 = hx0 + 1u;
        const unsigned hy0 = (unsigned)iy * 2654435761u, hy1 = hy0 + 2654435761u;
        const unsigned hz0 = (unsigned)iz * 805459861u,  hz1 = hz0 + 805459861u;
        const unsigned M = (unsigned)(TSZ - 1);
        idxs[0] = (hx0 ^ hy0 ^ hz0) & M;
        idxs[1] = (hx0 ^ hy0 ^ hz1) & M;
        idxs[2] = (hx0 ^ hy1 ^ hz0) & M;
        idxs[3] = (hx0 ^ hy1 ^ hz1) & M;
        idxs[4] = (hx1 ^ hy0 ^ hz0) & M;
        idxs[5] = (hx1 ^ hy0 ^ hz1) & M;
        idxs[6] = (hx1 ^ hy1 ^ hz0) & M;
        idxs[7] = (hx1 ^ hy1 ^ hz1) & M;
    }
}

__global__ __launch_bounds__(128, 4)
void sdf_kernel(const float* __restrict__ points,
                const float* __restrict__ table,
                float* __restrict__ out,
                int n, GridParams gp)
{
    __shared__ __align__(16) float sW0[DIN][HIDDEN];
    __shared__ __align__(16) float sW1[HIDDEN][HIDDEN];
    __shared__ __align__(16) float sW2[HIDDEN][16];
    __shared__ __align__(16) float sb0[HIDDEN];
    __shared__ __align__(16) float sb1[HIDDEN];
    __shared__ __align__(16) float sb2[16];

    const int tid = threadIdx.x;
    for (int i = tid; i < DIN * HIDDEN;    i += 128) (&sW0[0][0])[i] = (&g_W0T[0][0])[i];
    for (int i = tid; i < HIDDEN * HIDDEN; i += 128) (&sW1[0][0])[i] = (&g_W1T[0][0])[i];
    for (int i = tid; i < HIDDEN * 16;     i += 128) (&sW2[0][0])[i] = (&g_W2T[0][0])[i];
    if (tid < HIDDEN) { sb0[tid] = g_b0[tid]; sb1[tid] = g_b1[tid]; }
    if (tid < 16)     { sb2[tid] = g_b2[tid]; }
    __syncthreads();

    const int p = blockIdx.x * 128 + tid;
    if (p >= n) return;

    const float px = points[3 * p + 0];
    const float py = points[3 * p + 1];
    const float pz = points[3 * p + 2];
    const float ux = fminf(fmaxf((px + 1.f) * 0.5f, 0.f), 1.f);
    const float uy = fminf(fmaxf((py + 1.f) * 0.5f, 0.f), 1.f);
    const float uz = fminf(fmaxf((pz + 1.f) * 0.5f, 0.f), 1.f);

    // ---- layer 0: 32 packed accumulators (R2-style u64 shared loads) ----
    u64 acc[32];
    {
        const u64* b = (const u64*)sb0;
        #pragma unroll
        for (int j = 0; j < 32; j++) acc[j] = b[j];
    }
    {
        const u64* wa = (const u64*)&sW0[0][0];
        const u64* wb = (const u64*)&sW0[1][0];
        const u64* wc = (const u64*)&sW0[2][0];
        const u64 bx = bcast2(px), by = bcast2(py), bz = bcast2(pz);
        #pragma unroll
        for (int j = 0; j < 32; j++) {
            acc[j] = fma2(bx, wa[j], acc[j]);
            acc[j] = fma2(by, wb[j], acc[j]);
            acc[j] = fma2(bz, wc[j], acc[j]);
        }
    }

    const float2* __restrict__ tab = (const float2*)table;

    // ---- software-pipelined hashgrid levels -----------------------------
    float wxc, wyc, wzc;
    float2 fc[8];
    {
        unsigned idxs[8];
        level_setup(gp.gs[0], ux, uy, uz, idxs, wxc, wyc, wzc);
        #pragma unroll
        for (int c = 0; c < 8; c++) fc[c] = __ldg(&tab[idxs[c]]);
    }

    #pragma unroll 1
    for (int lv = 0; lv < NLEV; lv++) {
        float wxn = 0.f, wyn = 0.f, wzn = 0.f;
        float2 fn[8];
        #pragma unroll
        for (int c = 0; c < 8; c++) { fn[c].x = 0.f; fn[c].y = 0.f; }
        if (lv + 1 < NLEV) {
            unsigned idxs[8];
            level_setup(gp.gs[lv + 1], ux, uy, uz, idxs, wxn, wyn, wzn);
            const float2* __restrict__ tb = tab + (size_t)(lv + 1) * TSZ;
            #pragma unroll
            for (int c = 0; c < 8; c++) fn[c] = __ldg(&tb[idxs[c]]);
        }

        // consume current level: trilinear blend
        const float ox = 1.f - wxc, oy = 1.f - wyc, oz = 1.f - wzc;
        const float w0 = ox * oy * oz,   w1 = ox * oy * wzc;
        const float w2 = ox * wyc * oz,  w3 = ox * wyc * wzc;
        const float w4 = wxc * oy * oz,  w5 = wxc * oy * wzc;
        const float w6 = wxc * wyc * oz, w7 = wxc * wyc * wzc;
        const float f0 = fc[0].x * w0 + fc[1].x * w1 + fc[2].x * w2 + fc[3].x * w3
                       + fc[4].x * w4 + fc[5].x * w5 + fc[6].x * w6 + fc[7].x * w7;
        const float f1 = fc[0].y * w0 + fc[1].y * w1 + fc[2].y * w2 + fc[3].y * w3
                       + fc[4].y * w4 + fc[5].y * w5 + fc[6].y * w6 + fc[7].y * w7;

        const int r = 3 + 2 * lv;
        const u64* wa = (const u64*)&sW0[r][0];
        const u64* wb = (const u64*)&sW0[r + 1][0];
        const u64 bf0 = bcast2(f0), bf1 = bcast2(f1);
        #pragma unroll
        for (int j = 0; j < 32; j++) {
            acc[j] = fma2(bf0, wa[j], acc[j]);
            acc[j] = fma2(bf1, wb[j], acc[j]);
        }

        // rotate pipeline
        wxc = wxn; wyc = wyn; wzc = wzn;
        #pragma unroll
        for (int c = 0; c < 8; c++) fc[c] = fn[c];
    }

    // softplus -> scalar h[64]
    float h[HIDDEN];
    #pragma unroll
    for (int j = 0; j < 32; j++) {
        float lo, hi; unpack2(acc[j], lo, hi);
        h[2 * j]     = softplus100(lo);
        h[2 * j + 1] = softplus100(hi);
    }

    // ---- layer 1 --------------------------------------------------------
    u64 acc1[32];
    {
        const u64* b = (const u64*)sb1;
        #pragma unroll
        for (int j = 0; j < 32; j++) acc1[j] = b[j];
    }
    #pragma unroll 4
    for (int i = 0; i < HIDDEN; i++) {
        const u64 hb = bcast2(h[i]);
        const u64* w = (const u64*)&sW1[i][0];
        #pragma unroll
        for (int j = 0; j < 32; j++) acc1[j] = fma2(hb, w[j], acc1[j]);
    }
    float h1[HIDDEN];
    #pragma unroll
    for (int j = 0; j < 32; j++) {
        float lo, hi; unpack2(acc1[j], lo, hi);
        h1[2 * j]     = softplus100(lo);
        h1[2 * j + 1] = softplus100(hi);
    }

    // ---- layer 2 --------------------------------------------------------
    u64 acc2[8];
    {
        const u64* b = (const u64*)sb2;
        #pragma unroll
        for (int j = 0; j < 8; j++) acc2[j] = b[j];
    }
    #pragma unroll 8
    for (int i = 0; i < HIDDEN; i++) {
        const u64 hb = bcast2(h1[i]);
        const u64* w = (const u64*)&sW2[i][0];
        #pragma unroll
        for (int j = 0; j < 8; j++) acc2[j] = fma2(hb, w[j], acc2[j]);
    }

    float o2[16];
    #pragma unroll
    for (int j = 0; j < 8; j++) unpack2(acc2[j], o2[2 * j], o2[2 * j + 1]);

    out[p] = o2[0];
    float* __restrict__ hout = out + n + (size_t)p * FEAT;
    #pragma unroll
    for (int j = 0; j < FEAT; j++) hout[j] = o2[j];
}

extern "C" void kernel_launch(void* const* d_in, const int* in_sizes, int n_in,
                              void* d_out, int out_size)
{
    const float* points = (const float*)d_in[0];
    const float* table  = (const float*)d_in[1];
    const float* V0 = (const float*)d_in[2];
    const float* g0 = (const float*)d_in[3];
    const float* b0 = (const float*)d_in[4];
    const float* V1 = (const float*)d_in[5];
    const float* g1 = (const float*)d_in[6];
    const float* b1 = (const float*)d_in[7];
    const float* V2 = (const float*)d_in[8];
    const float* g2 = (const float*)d_in[9];
    const float* b2 = (const float*)d_in[10];
    float* out = (float*)d_out;

    const int n = in_sizes[0] / 3;

    GridParams gp;
    const double scale = exp((log(2048.0) - log(16.0)) / 15.0);
    for (int lv = 0; lv < NLEV; lv++)
        gp.gs[lv] = (int)floor(16.0 * pow(scale, (double)lv)) + 1;

    prep_kernel<<<1, 64>>>(V0, g0, b0, V1, g1, b1, V2, g2, b2);

    const int blocks = (n + 127) / 128;
    sdf_kernel<<<blocks, 128>>>(points, table, out, n, gp);
}

// round 6
// speedup vs baseline: 1.4864x; 1.0315x over previous
#include <cuda_runtime.h>
#include <math.h>

#define NLEV   16
#define TSZ    524288
#define HIDDEN 64
#define FEAT   13
#define DIN    35

typedef unsigned long long u64;

__device__ __forceinline__ u64 pack2(float lo, float hi) {
    u64 r; asm("mov.b64 %0, {%1, %2};" : "=l"(r) : "f"(lo), "f"(hi)); return r;
}
__device__ __forceinline__ u64 bcast2(float v) { return pack2(v, v); }
__device__ __forceinline__ u64 fma2(u64 a, u64 b, u64 c) {
    u64 d; asm("fma.rn.f32x2 %0, %1, %2, %3;" : "=l"(d) : "l"(a), "l"(b), "l"(c)); return d;
}
__device__ __forceinline__ void unpack2(u64 v, float& lo, float& hi) {
    asm("mov.b64 {%0, %1}, %2;" : "=f"(lo), "=f"(hi) : "l"(v));
}

// ---------------------------------------------------------------------------
// Stage 1: float staging arrays (weight-norm applied, transposed [in][out])
// ---------------------------------------------------------------------------
__device__ float g_W0T[DIN][HIDDEN];
__device__ float g_W1T[HIDDEN][HIDDEN];
__device__ float g_W2T[HIDDEN][16];
__device__ float g_b0[HIDDEN];
__device__ float g_b1[HIDDEN];
__device__ float g_b2[16];

// Stage 2: value-packed ulonglong2 arrays (native wide type, no punning)
__device__ ulonglong2 g_W0p[DIN][16];      // row = 64 floats = 16 ull2
__device__ ulonglong2 g_W1p[HIDDEN][16];
__device__ ulonglong2 g_W2p[HIDDEN][4];    // row = 16 floats = 4 ull2
__device__ ulonglong2 g_b0p[16];
__device__ ulonglong2 g_b1p[16];
__device__ ulonglong2 g_b2p[4];

__global__ void prep_kernel(const float* __restrict__ V0, const float* __restrict__ g0, const float* __restrict__ b0,
                            const float* __restrict__ V1, const float* __restrict__ g1, const float* __restrict__ b1,
                            const float* __restrict__ V2, const float* __restrict__ g2, const float* __restrict__ b2)
{
    int o = threadIdx.x;
    if (o < HIDDEN) {
        float s = 0.f;
        for (int i = 0; i < DIN; i++) { float v = V0[o * DIN + i]; s += v * v; }
        float sc = g0[o] / sqrtf(s);
        for (int i = 0; i < DIN; i++) g_W0T[i][o] = V0[o * DIN + i] * sc;
        g_b0[o] = b0[o];

        s = 0.f;
        for (int i = 0; i < HIDDEN; i++) { float v = V1[o * HIDDEN + i]; s += v * v; }
        sc = g1[o] / sqrtf(s);
        for (int i = 0; i < HIDDEN; i++) g_W1T[i][o] = V1[o * HIDDEN + i] * sc;
        g_b1[o] = b1[o];
    }
    if (o < 16) {
        if (o < FEAT) {
            float s = 0.f;
            for (int i = 0; i < HIDDEN; i++) { float v = V2[o * HIDDEN + i]; s += v * v; }
            float sc = g2[o] / sqrtf(s);
            for (int i = 0; i < HIDDEN; i++) g_W2T[i][o] = V2[o * HIDDEN + i] * sc;
            g_b2[o] = b2[o];
        } else {
            for (int i = 0; i < HIDDEN; i++) g_W2T[i][o] = 0.f;
            g_b2[o] = 0.f;
        }
    }
}

// Pack 4 consecutive floats into one ulonglong2, purely by value.
__device__ __forceinline__ ulonglong2 pack4(const float* s) {
    ulonglong2 v;
    v.x = ((u64)__float_as_uint(s[1]) << 32) | (u64)__float_as_uint(s[0]);
    v.y = ((u64)__float_as_uint(s[3]) << 32) | (u64)__float_as_uint(s[2]);
    return v;
}

__global__ void pack_kernel()
{
    const int NW0 = DIN * 16, NW1 = HIDDEN * 16, NW2 = HIDDEN * 4;
    const int total = NW0 + NW1 + NW2 + 16 + 16 + 4;
    for (int e = threadIdx.x; e < total; e += blockDim.x) {
        int r = e;
        if (r < NW0) { (&g_W0p[0][0])[r] = pack4(&(&g_W0T[0][0])[4 * r]); continue; }
        r -= NW0;
        if (r < NW1) { (&g_W1p[0][0])[r] = pack4(&(&g_W1T[0][0])[4 * r]); continue; }
        r -= NW1;
        if (r < NW2) { (&g_W2p[0][0])[r] = pack4(&(&g_W2T[0][0])[4 * r]); continue; }
        r -= NW2;
        if (r < 16) { g_b0p[r] = pack4(&g_b0[4 * r]); continue; }
        r -= 16;
        if (r < 16) { g_b1p[r] = pack4(&g_b1[4 * r]); continue; }
        r -= 16;
        g_b2p[r] = pack4(&g_b2[4 * r]);
    }
}

struct GridParams { int gs[NLEV]; };

__device__ __forceinline__ float softplus100(float z)
{
    float x = 100.f * z;
    return (fmaxf(x, 0.f) + log1pf(__expf(-fabsf(x)))) * 0.01f;
}

// Corner order: c = i*4 + j*2 + k (matches reference OFFSETS loop nest).
__device__ __forceinline__ void level_setup(int gs, float ux, float uy, float uz,
                                            unsigned idxs[8], float& wx, float& wy, float& wz)
{
    const float gm1 = (float)(gs - 1);
    const float fx = ux * gm1, fy = uy * gm1, fz = uz * gm1;
    int ix = (int)floorf(fx); ix = min(max(ix, 0), gs - 2);
    int iy = (int)floorf(fy); iy = min(max(iy, 0), gs - 2);
    int iz = (int)floorf(fz); iz = min(max(iz, 0), gs - 2);
    wx = fx - (float)ix;
    wy = fy - (float)iy;
    wz = fz - (float)iz;

    if ((long long)gs * gs * gs <= (long long)TSZ) {
        const int g1 = gs, g2 = gs * gs;
        const int base = ix + g1 * iy + g2 * iz;
        idxs[0] = base;
        idxs[1] = base + g2;
        idxs[2] = base + g1;
        idxs[3] = base + g1 + g2;
        idxs[4] = base + 1;
        idxs[5] = base + 1 + g2;
        idxs[6] = base + 1 + g1;
        idxs[7] = base + 1 + g1 + g2;
    } else {
        const unsigned hx0 = (unsigned)ix,               hx1 = hx0 + 1u;
        const unsigned hy0 = (unsigned)iy * 2654435761u, hy1 = hy0 + 2654435761u;
        const unsigned hz0 = (unsigned)iz * 805459861u,  hz1 = hz0 + 805459861u;
        const unsigned M = (unsigned)(TSZ - 1);
        idxs[0] = (hx0 ^ hy0 ^ hz0) & M;
        idxs[1] = (hx0 ^ hy0 ^ hz1) & M;
        idxs[2] = (hx0 ^ hy1 ^ hz0) & M;
        idxs[3] = (hx0 ^ hy1 ^ hz1) & M;
        idxs[4] = (hx1 ^ hy0 ^ hz0) & M;
        idxs[5] = (hx1 ^ hy0 ^ hz1) & M;
        idxs[6] = (hx1 ^ hy1 ^ hz0) & M;
        idxs[7] = (hx1 ^ hy1 ^ hz1) & M;
    }
}

__global__ __launch_bounds__(128, 4)
void sdf_kernel(const float* __restrict__ points,
                const float* __restrict__ table,
                float* __restrict__ out,
                int n, GridParams gp)
{
    __shared__ ulonglong2 sW0[DIN][16];
    __shared__ ulonglong2 sW1[HIDDEN][16];
    __shared__ ulonglong2 sW2[HIDDEN][4];
    __shared__ ulonglong2 sb0[16];
    __shared__ ulonglong2 sb1[16];
    __shared__ ulonglong2 sb2[4];

    const int tid = threadIdx.x;
    for (int i = tid; i < DIN * 16;    i += 128) (&sW0[0][0])[i] = (&g_W0p[0][0])[i];
    for (int i = tid; i < HIDDEN * 16; i += 128) (&sW1[0][0])[i] = (&g_W1p[0][0])[i];
    for (int i = tid; i < HIDDEN * 4;  i += 128) (&sW2[0][0])[i] = (&g_W2p[0][0])[i];
    if (tid < 16) { sb0[tid] = g_b0p[tid]; sb1[tid] = g_b1p[tid]; }
    if (tid < 4)  { sb2[tid] = g_b2p[tid]; }
    __syncthreads();

    const int p = blockIdx.x * 128 + tid;
    if (p >= n) return;

    const float px = points[3 * p + 0];
    const float py = points[3 * p + 1];
    const float pz = points[3 * p + 2];
    const float ux = fminf(fmaxf((px + 1.f) * 0.5f, 0.f), 1.f);
    const float uy = fminf(fmaxf((py + 1.f) * 0.5f, 0.f), 1.f);
    const float uz = fminf(fmaxf((pz + 1.f) * 0.5f, 0.f), 1.f);

    // ---- layer 0: 32 packed accumulators, xyz contribution --------------
    u64 acc[32];
    #pragma unroll
    for (int q = 0; q < 16; q++) {
        const ulonglong2 b = sb0[q];
        acc[2 * q] = b.x; acc[2 * q + 1] = b.y;
    }
    {
        const u64 bx = bcast2(px), by = bcast2(py), bz = bcast2(pz);
        #pragma unroll
        for (int q = 0; q < 16; q++) {
            const ulonglong2 va = sW0[0][q];
            const ulonglong2 vb = sW0[1][q];
            const ulonglong2 vc = sW0[2][q];
            acc[2 * q]     = fma2(bx, va.x, acc[2 * q]);
            acc[2 * q + 1] = fma2(bx, va.y, acc[2 * q + 1]);
            acc[2 * q]     = fma2(by, vb.x, acc[2 * q]);
            acc[2 * q + 1] = fma2(by, vb.y, acc[2 * q + 1]);
            acc[2 * q]     = fma2(bz, vc.x, acc[2 * q]);
            acc[2 * q + 1] = fma2(bz, vc.y, acc[2 * q + 1]);
        }
    }

    const float2* __restrict__ tab = (const float2*)table;

    // ---- software-pipelined hashgrid levels -----------------------------
    float wxc, wyc, wzc;
    float2 fc[8];
    {
        unsigned idxs[8];
        level_setup(gp.gs[0], ux, uy, uz, idxs, wxc, wyc, wzc);
        #pragma unroll
        for (int c = 0; c < 8; c++) fc[c] = __ldg(&tab[idxs[c]]);
    }

    #pragma unroll 1
    for (int lv = 0; lv < NLEV; lv++) {
        float wxn = 0.f, wyn = 0.f, wzn = 0.f;
        float2 fn[8];
        #pragma unroll
        for (int c = 0; c < 8; c++) { fn[c].x = 0.f; fn[c].y = 0.f; }
        if (lv + 1 < NLEV) {
            unsigned idxs[8];
            level_setup(gp.gs[lv + 1], ux, uy, uz, idxs, wxn, wyn, wzn);
            const float2* __restrict__ tb = tab + (size_t)(lv + 1) * TSZ;
            #pragma unroll
            for (int c = 0; c < 8; c++) fn[c] = __ldg(&tb[idxs[c]]);
        }

        // consume current level: trilinear blend
        const float ox = 1.f - wxc, oy = 1.f - wyc, oz = 1.f - wzc;
        const float w0 = ox * oy * oz,   w1 = ox * oy * wzc;
        const float w2 = ox * wyc * oz,  w3 = ox * wyc * wzc;
        const float w4 = wxc * oy * oz,  w5 = wxc * oy * wzc;
        const float w6 = wxc * wyc * oz, w7 = wxc * wyc * wzc;
        const float f0 = fc[0].x * w0 + fc[1].x * w1 + fc[2].x * w2 + fc[3].x * w3
                       + fc[4].x * w4 + fc[5].x * w5 + fc[6].x * w6 + fc[7].x * w7;
        const float f1 = fc[0].y * w0 + fc[1].y * w1 + fc[2].y * w2 + fc[3].y * w3
                       + fc[4].y * w4 + fc[5].y * w5 + fc[6].y * w6 + fc[7].y * w7;

        const int r = 3 + 2 * lv;
        const u64 bf0 = bcast2(f0), bf1 = bcast2(f1);
        #pragma unroll
        for (int q = 0; q < 16; q++) {
            const ulonglong2 va = sW0[r][q];
            const ulonglong2 vb = sW0[r + 1][q];
            acc[2 * q]     = fma2(bf0, va.x, acc[2 * q]);
            acc[2 * q + 1] = fma2(bf0, va.y, acc[2 * q + 1]);
            acc[2 * q]     = fma2(bf1, vb.x, acc[2 * q]);
            acc[2 * q + 1] = fma2(bf1, vb.y, acc[2 * q + 1]);
        }

        // rotate pipeline
        wxc = wxn; wyc = wyn; wzc = wzn;
        #pragma unroll
        for (int c = 0; c < 8; c++) fc[c] = fn[c];
    }

    // softplus -> scalar h[64]
    float h[HIDDEN];
    #pragma unroll
    for (int j = 0; j < 32; j++) {
        float lo, hi; unpack2(acc[j], lo, hi);
        h[2 * j]     = softplus100(lo);
        h[2 * j + 1] = softplus100(hi);
    }

    // ---- layer 1 --------------------------------------------------------
    u64 acc1[32];
    #pragma unroll
    for (int q = 0; q < 16; q++) {
        const ulonglong2 b = sb1[q];
        acc1[2 * q] = b.x; acc1[2 * q + 1] = b.y;
    }
    #pragma unroll 4
    for (int i = 0; i < HIDDEN; i++) {
        const u64 hb = bcast2(h[i]);
        #pragma unroll
        for (int q = 0; q < 16; q++) {
            const ulonglong2 v = sW1[i][q];
            acc1[2 * q]     = fma2(hb, v.x, acc1[2 * q]);
            acc1[2 * q + 1] = fma2(hb, v.y, acc1[2 * q + 1]);
        }
    }
    float h1[HIDDEN];
    #pragma unroll
    for (int j = 0; j < 32; j++) {
        float lo, hi; unpack2(acc1[j], lo, hi);
        h1[2 * j]     = softplus100(lo);
        h1[2 * j + 1] = softplus100(hi);
    }

    // ---- layer 2 --------------------------------------------------------
    u64 acc2[8];
    #pragma unroll
    for (int q = 0; q < 4; q++) {
        const ulonglong2 b = sb2[q];
        acc2[2 * q] = b.x; acc2[2 * q + 1] = b.y;
    }
    #pragma unroll 8
    for (int i = 0; i < HIDDEN; i++) {
        const u64 hb = bcast2(h1[i]);
        #pragma unroll
        for (int q = 0; q < 4; q++) {
            const ulonglong2 v = sW2[i][q];
            acc2[2 * q]     = fma2(hb, v.x, acc2[2 * q]);
            acc2[2 * q + 1] = fma2(hb, v.y, acc2[2 * q + 1]);
        }
    }

    float o2[16];
    #pragma unroll
    for (int j = 0; j < 8; j++) unpack2(acc2[j], o2[2 * j], o2[2 * j + 1]);

    out[p] = o2[0];
    float* __restrict__ hout = out + n + (size_t)p * FEAT;
    #pragma unroll
    for (int j = 0; j < FEAT; j++) hout[j] = o2[j];
}

extern "C" void kernel_launch(void* const* d_in, const int* in_sizes, int n_in,
                              void* d_out, int out_size)
{
    const float* points = (const float*)d_in[0];
    const float* table  = (const float*)d_in[1];
    const float* V0 = (const float*)d_in[2];
    const float* g0 = (const float*)d_in[3];
    const float* b0 = (const float*)d_in[4];
    const float* V1 = (const float*)d_in[5];
    const float* g1 = (const float*)d_in[6];
    const float* b1 = (const float*)d_in[7];
    const float* V2 = (const float*)d_in[8];
    const float* g2 = (const float*)d_in[9];
    const float* b2 = (const float*)d_in[10];
    float* out = (float*)d_out;

    const int n = in_sizes[0] / 3;

    GridParams gp;
    const double scale = exp((log(2048.0) - log(16.0)) / 15.0);
    for (int lv = 0; lv < NLEV; lv++)
        gp.gs[lv] = (int)floor(16.0 * pow(scale, (double)lv)) + 1;

    prep_kernel<<<1, 64>>>(V0, g0, b0, V1, g1, b1, V2, g2, b2);
    pack_kernel<<<1, 256>>>();

    const int blocks = (n + 127) / 128;
    sdf_kernel<<<blocks, 128>>>(points, table, out, n, gp);
}